// round 1
// baseline (speedup 1.0000x reference)
#include <cuda_runtime.h>
#include <cuda_bf16.h>

// Shapes (fixed by the problem):
//  x [2,31,128,128]; conv head k3 s2 p1 -> y [2,64,64,64]; N=4096 nodes/batch.
//  kNN: 7 nearest (incl self) by (clip(d2,0), j) lexicographic (== stable double-argsort rank<=6).
//  GAT heads 64->64 (x2, concat+relu), out 128->64, elu, log_softmax(C).
//  ConvT k3 s2 p1 op1 -> out [2,64,128,128].

#define NB 2
#define NPB 4096           // nodes per batch (64x64)
#define NTOT (NB*NPB)      // 8192
#define C 64

// ---------------- scratch (device globals; no allocation) ----------------
__device__ float g_y[NTOT*C];        // conv-head output, channel-last
__device__ float g_sq[NTOT];         // ||y_i||^2
__device__ int   g_nbr[NTOT*7];      // 7 neighbor indices (within batch)
__device__ float g_h0[NTOT*C], g_h1[NTOT*C];
__device__ float g_f10[NTOT], g_f20[NTOT], g_f11[NTOT], g_f21[NTOT];
__device__ float g_hcat[NTOT*2*C];
__device__ float g_ho[NTOT*C];
__device__ float g_f1o[NTOT], g_f2o[NTOT];
__device__ float g_outn[NTOT*C];     // after elu+log_softmax, [node][c]
__device__ float g_wt[9*64*64];      // repacked convT weights [k][ci][co]

// ---------------- K0: repack convT weights ----------------
__global__ void repack_kernel(const float* __restrict__ w_last) {
    int idx = blockIdx.x * 256 + threadIdx.x;
    if (idx >= 64*64*9) return;
    int co = idx & 63;
    int ci = (idx >> 6) & 63;
    int k  = idx >> 12;                 // kh*3+kw
    // w_last layout [ci][co][kh][kw]
    g_wt[(k*64 + ci)*64 + co] = w_last[(ci*64 + co)*9 + k];
}

// ---------------- K1: conv head + per-node squared norm ----------------
__global__ void conv_head_kernel(const float* __restrict__ x,
                                 const float* __restrict__ w,
                                 const float* __restrict__ bias) {
    int blk = blockIdx.x;               // b*4096 + node
    int b = blk >> 12;
    int node = blk & 4095;
    int oh = node >> 6, ow = node & 63;
    __shared__ float patch[31*9];
    __shared__ float s2[64];
    int t = threadIdx.x;                // 64 threads
    for (int idx = t; idx < 31*9; idx += 64) {
        int ci = idx / 9, k = idx % 9;
        int kh = k / 3, kw = k % 3;
        int ih = oh*2 - 1 + kh, iw = ow*2 - 1 + kw;
        float v = 0.f;
        if ((unsigned)ih < 128u && (unsigned)iw < 128u)
            v = x[((b*31 + ci)*128 + ih)*128 + iw];
        patch[idx] = v;
    }
    __syncthreads();
    float acc = bias[t];
    const float* wp = &w[t*279];
    #pragma unroll 9
    for (int k = 0; k < 279; k++) acc += patch[k] * wp[k];
    g_y[blk*64 + t] = acc;
    s2[t] = acc*acc;
    __syncthreads();
    if (t == 0) {
        float q = 0.f;
        for (int k = 0; k < 64; k++) q += s2[k];
        g_sq[blk] = q;
    }
}

// ---------------- K2: fused Gram + top-7 kNN selection ----------------
// Block handles 16 i-rows; 256 threads; thread t: i_local = t&15, group g=t>>4.
#define TI 16
#define TJ 64
__global__ void knn_kernel() {
    __shared__ float yi[TI*67];
    __shared__ float sqi[TI];
    __shared__ float yj[TJ*67];
    __shared__ float sqj[TJ];
    __shared__ float cd[256*7];
    __shared__ int   cjj[256*7];
    int t = threadIdx.x;
    int i0 = blockIdx.x * TI;           // global node index
    int base = (i0 >> 12) << 12;        // batch base
    for (int idx = t; idx < TI*64; idx += 256) {
        int il = idx >> 6, c = idx & 63;
        yi[il*67 + c] = g_y[(i0 + il)*64 + c];
    }
    if (t < TI) sqi[t] = g_sq[i0 + t];
    int il = t & 15, g = t >> 4;
    float bd[7]; int bj[7];
    #pragma unroll
    for (int s = 0; s < 7; s++) { bd[s] = 3.4e38f; bj[s] = 0x7fffffff; }

    for (int jt = 0; jt < NPB; jt += TJ) {
        __syncthreads();
        for (int idx = t; idx < TJ*64; idx += 256) {
            int jl = idx >> 6, c = idx & 63;
            yj[jl*67 + c] = g_y[(base + jt + jl)*64 + c];
        }
        if (t < TJ) sqj[t] = g_sq[base + jt + t];
        __syncthreads();
        const float* pi = &yi[il*67];
        float sqv = sqi[il];
        #pragma unroll
        for (int m = 0; m < TJ/16; m++) {
            int jl = g + m*16;
            const float* pj = &yj[jl*67];
            float acc = 0.f;
            #pragma unroll
            for (int c2 = 0; c2 < 64; c2++) acc += pi[c2] * pj[c2];
            float d2 = sqv + sqj[jl] - 2.f*acc;
            if (d2 < 0.f) d2 = 0.f;
            int j = jt + jl;
            if (d2 < bd[6] || (d2 == bd[6] && j < bj[6])) {
                bd[6] = d2; bj[6] = j;
                #pragma unroll
                for (int s = 5; s >= 0; s--) {
                    bool sw = (bd[s+1] < bd[s]) || (bd[s+1] == bd[s] && bj[s+1] < bj[s]);
                    if (sw) {
                        float td = bd[s]; bd[s] = bd[s+1]; bd[s+1] = td;
                        int tj = bj[s]; bj[s] = bj[s+1]; bj[s+1] = tj;
                    }
                }
            }
        }
    }
    #pragma unroll
    for (int s = 0; s < 7; s++) { cd[t*7 + s] = bd[s]; cjj[t*7 + s] = bj[s]; }
    __syncthreads();
    if (t < TI) {
        int ptr[16];
        #pragma unroll
        for (int g2 = 0; g2 < 16; g2++) ptr[g2] = 0;
        for (int s = 0; s < 7; s++) {
            float best = 3.5e38f; int bestj = 0x7fffffff; int bg = 0;
            for (int g2 = 0; g2 < 16; g2++) {
                int th = g2*16 + t;
                int p = ptr[g2];
                float d = cd[th*7 + p]; int j = cjj[th*7 + p];
                if (d < best || (d == best && j < bestj)) { best = d; bestj = j; bg = g2; }
            }
            ptr[bg]++;
            g_nbr[(i0 + t)*7 + s] = bestj;
        }
    }
}

// ---------------- K3: project heads 0/1 + attention scalars ----------------
__global__ void proj01_kernel(const float* __restrict__ W0, const float* __restrict__ a0,
                              const float* __restrict__ W1, const float* __restrict__ a1) {
    int node = blockIdx.x;
    int t = threadIdx.x;                // 128
    __shared__ float yr[64];
    __shared__ float hs[128];
    if (t < 64) yr[t] = g_y[node*64 + t];
    __syncthreads();
    int c = t & 63;
    const float* W = (t < 64) ? W0 : W1;
    float acc = 0.f;
    #pragma unroll
    for (int k = 0; k < 64; k++) acc += yr[k] * W[k*64 + c];
    hs[t] = acc;
    if (t < 64) g_h0[node*64 + c] = acc; else g_h1[node*64 + c] = acc;
    __syncthreads();
    if (t == 0) {
        float f1 = 0.f, f2 = 0.f;
        for (int k = 0; k < 64; k++) { f1 += hs[k]*a0[k]; f2 += hs[k]*a0[64 + k]; }
        g_f10[node] = f1; g_f20[node] = f2;
    } else if (t == 64) {
        float f1 = 0.f, f2 = 0.f;
        for (int k = 0; k < 64; k++) { f1 += hs[64 + k]*a1[k]; f2 += hs[64 + k]*a1[64 + k]; }
        g_f11[node] = f1; g_f21[node] = f2;
    }
}

// ---------------- K4: sparse attention aggregation, heads 0/1, relu ----------------
__global__ void agg01_kernel() {
    int node = blockIdx.x;
    int t = threadIdx.x;                // 128
    int head = t >> 6, c = t & 63;
    int bb = (node >> 12) << 12;
    int nb[7];
    #pragma unroll
    for (int s = 0; s < 7; s++) nb[s] = bb + g_nbr[node*7 + s];
    const float* f1 = head ? g_f11 : g_f10;
    const float* f2 = head ? g_f21 : g_f20;
    const float* h  = head ? g_h1  : g_h0;
    float fi = f1[node];
    float e[7], m = -3.4e38f;
    #pragma unroll
    for (int s = 0; s < 7; s++) {
        float v = fi + f2[nb[s]];
        v = v > 0.f ? v : 0.2f*v;       // leaky relu alpha=0.2
        e[s] = v; if (v > m) m = v;
    }
    float sum = 0.f;
    #pragma unroll
    for (int s = 0; s < 7; s++) { e[s] = expf(e[s] - m); sum += e[s]; }
    float inv = 1.f / sum;
    float acc = 0.f;
    #pragma unroll
    for (int s = 0; s < 7; s++) acc += e[s]*inv * h[nb[s]*64 + c];
    acc = acc > 0.f ? acc : 0.f;        // relu (concat head)
    g_hcat[node*128 + head*64 + c] = acc;
}

// ---------------- K5: project out head (128->64) + attention scalars ----------------
__global__ void projout_kernel(const float* __restrict__ W_out, const float* __restrict__ a_out) {
    int node = blockIdx.x;
    int t = threadIdx.x;                // 64
    __shared__ float hr[128];
    __shared__ float hos[64];
    hr[t]      = g_hcat[node*128 + t];
    hr[t + 64] = g_hcat[node*128 + 64 + t];
    __syncthreads();
    float acc = 0.f;
    #pragma unroll
    for (int k = 0; k < 128; k++) acc += hr[k] * W_out[k*64 + t];
    hos[t] = acc;
    g_ho[node*64 + t] = acc;
    __syncthreads();
    if (t == 0) {
        float f1 = 0.f, f2 = 0.f;
        for (int k = 0; k < 64; k++) { f1 += hos[k]*a_out[k]; f2 += hos[k]*a_out[64 + k]; }
        g_f1o[node] = f1; g_f2o[node] = f2;
    }
}

// ---------------- K6: out-head aggregation + elu + log_softmax ----------------
__global__ void aggout_kernel() {
    int node = blockIdx.x;
    int t = threadIdx.x;                // 64
    int bb = (node >> 12) << 12;
    __shared__ float vs[64];
    __shared__ float srm[2];
    int nb[7];
    #pragma unroll
    for (int s = 0; s < 7; s++) nb[s] = bb + g_nbr[node*7 + s];
    float fi = g_f1o[node];
    float e[7], m = -3.4e38f;
    #pragma unroll
    for (int s = 0; s < 7; s++) {
        float v = fi + g_f2o[nb[s]];
        v = v > 0.f ? v : 0.2f*v;
        e[s] = v; if (v > m) m = v;
    }
    float sum = 0.f;
    #pragma unroll
    for (int s = 0; s < 7; s++) { e[s] = expf(e[s] - m); sum += e[s]; }
    float inv = 1.f / sum;
    float acc = 0.f;
    #pragma unroll
    for (int s = 0; s < 7; s++) acc += e[s]*inv * g_ho[nb[s]*64 + t];
    float v = acc > 0.f ? acc : (expf(acc) - 1.f);   // elu
    vs[t] = v;
    __syncthreads();
    if (t == 0) {
        float mx = vs[0];
        for (int k = 1; k < 64; k++) mx = fmaxf(mx, vs[k]);
        float s2 = 0.f;
        for (int k = 0; k < 64; k++) s2 += expf(vs[k] - mx);
        srm[0] = mx; srm[1] = logf(s2);
    }
    __syncthreads();
    g_outn[node*64 + t] = vs[t] - srm[0] - srm[1];
}

// ---------------- K7: ConvTranspose2d (k3, s2, p1, op1) ----------------
__global__ void convt_kernel(const float* __restrict__ b_last, float* __restrict__ out) {
    int bo = blockIdx.x;                 // b*128 + oh
    int b = bo >> 7;
    int oh = bo & 127;
    __shared__ float sin[2][64*65];      // [row][iw*65+ci], padded vs conflicts
    int khs[2], ihs[2];
    int cnt = 0;
    for (int kh = 0; kh < 3; kh++) {
        int num = oh + 1 - kh;
        if (num & 1) continue;
        int ih = num >> 1;
        if (ih < 0 || ih >= 64) continue;
        khs[cnt] = kh; ihs[cnt] = ih; cnt++;
    }
    int t = threadIdx.x;                 // 256
    for (int r = 0; r < cnt; r++) {
        const float* src = &g_outn[((b << 12) + ihs[r]*64)*64];
        for (int idx = t; idx < 4096; idx += 256) {
            int iw = idx >> 6, ci = idx & 63;
            sin[r][iw*65 + ci] = src[idx];
        }
    }
    __syncthreads();
    for (int idx = t; idx < 8192; idx += 256) {
        int ow = idx & 127;
        int co = idx >> 7;
        float acc = b_last[co];
        for (int r = 0; r < cnt; r++) {
            int kh = khs[r];
            for (int kw = 0; kw < 3; kw++) {
                int num = ow + 1 - kw;
                if (num & 1) continue;
                int iw = num >> 1;
                if ((unsigned)iw >= 64u) continue;
                const float* pin = &sin[r][iw*65];
                const float* pw = &g_wt[(kh*3 + kw)*4096 + co];
                float a2 = 0.f;
                #pragma unroll
                for (int ci = 0; ci < 64; ci++) a2 += pin[ci] * pw[ci*64];
                acc += a2;
            }
        }
        out[((b*64 + co)*128 + oh)*128 + ow] = acc;
    }
}

// ---------------- launcher ----------------
extern "C" void kernel_launch(void* const* d_in, const int* in_sizes, int n_in,
                              void* d_out, int out_size) {
    const float* x      = (const float*)d_in[0];
    const float* w_head = (const float*)d_in[1];
    const float* b_head = (const float*)d_in[2];
    const float* W0     = (const float*)d_in[3];
    const float* a0     = (const float*)d_in[4];
    const float* W1     = (const float*)d_in[5];
    const float* a1     = (const float*)d_in[6];
    const float* W_out  = (const float*)d_in[7];
    const float* a_out  = (const float*)d_in[8];
    const float* w_last = (const float*)d_in[9];
    const float* b_last = (const float*)d_in[10];
    float* out = (float*)d_out;

    repack_kernel<<<144, 256>>>(w_last);
    conv_head_kernel<<<NTOT, 64>>>(x, w_head, b_head);
    knn_kernel<<<NTOT/TI, 256>>>();
    proj01_kernel<<<NTOT, 128>>>(W0, a0, W1, a1);
    agg01_kernel<<<NTOT, 128>>>();
    projout_kernel<<<NTOT, 64>>>(W_out, a_out);
    aggout_kernel<<<NTOT, 64>>>();
    convt_kernel<<<NB*128, 256>>>(b_last, out);
}

// round 3
// speedup vs baseline: 2.8321x; 2.8321x over previous
#include <cuda_runtime.h>
#include <cuda_bf16.h>

typedef unsigned long long ull;

#define NB 2
#define NPB 4096
#define NTOT (NB*NPB)
#define ULLMAX 0xFFFFFFFFFFFFFFFFull

// ---------------- scratch ----------------
__device__ float g_y[NTOT*64];
__device__ float g_sq[NTOT];
__device__ int   g_nbr[NTOT*7];
__device__ float g_h0[NTOT*64], g_h1[NTOT*64];
__device__ float g_f10[NTOT], g_f20[NTOT], g_f11[NTOT], g_f21[NTOT];
__device__ float g_hcat[NTOT*128];
__device__ float g_ho[NTOT*64];
__device__ float g_f1o[NTOT], g_f2o[NTOT];
__device__ float g_outn[NTOT*64];
__device__ float g_wt[9*64*64];      // convT weights [k][ci][co]
__device__ float g_wc[31*9*64];      // conv-head weights [ci*9+k][co]
__device__ float g_va[4*64];         // folded attention vecs heads 0/1
__device__ float g_vaO[2*128];       // folded attention vecs out head

// ---------------- K0: prep (repacks + folded attention vectors) ----------------
__global__ void prep_kernel(const float* __restrict__ w_last,
                            const float* __restrict__ w_head,
                            const float* __restrict__ W0, const float* __restrict__ a0,
                            const float* __restrict__ W1, const float* __restrict__ a1,
                            const float* __restrict__ W_out, const float* __restrict__ a_out) {
    int idx = blockIdx.x * 256 + threadIdx.x;
    if (idx < 36864) {
        int co = idx & 63, ci = (idx >> 6) & 63, k = idx >> 12;
        g_wt[(k*64 + ci)*64 + co] = w_last[(ci*64 + co)*9 + k];
    } else if (idx < 36864 + 17856) {
        int j = idx - 36864;          // j = (ci*9+k)*64+co
        int co = j & 63, rest = j >> 6;
        int k = rest % 9, ci = rest / 9;
        g_wc[j] = w_head[(co*31 + ci)*9 + k];
    } else if (idx < 36864 + 17856 + 256) {
        int j = idx - 54720;
        int head = j >> 7, which = (j >> 6) & 1, k = j & 63;
        const float* W = head ? W1 : W0;
        const float* a = head ? a1 : a0;
        float s = 0.f;
        for (int c = 0; c < 64; c++) s += W[k*64 + c] * a[which*64 + c];
        g_va[(head*2 + which)*64 + k] = s;
    } else if (idx < 36864 + 17856 + 512) {
        int j = idx - 54976;
        int which = j >> 7, k = j & 127;
        float s = 0.f;
        for (int c = 0; c < 64; c++) s += W_out[k*64 + c] * a_out[which*64 + c];
        g_vaO[which*128 + k] = s;
    }
}

// ---------------- K1: conv head (k3 s2 p1), register tiled ----------------
__global__ void conv_head_kernel(const float* __restrict__ x,
                                 const float* __restrict__ bias) {
    int b = blockIdx.x >> 6;
    int oh = blockIdx.x & 63;
    __shared__ float sIn[31*3*130];   // [ci][kh][iwp], iwp = iw+1
    int t = threadIdx.x;              // 256
    for (int idx = t; idx < 31*3*130; idx += 256) {
        int iwp = idx % 130;
        int rem = idx / 130;
        int r = rem % 3, ci = rem / 3;
        int ih = oh*2 - 1 + r, iw = iwp - 1;
        float v = 0.f;
        if ((unsigned)ih < 128u && (unsigned)iw < 128u)
            v = x[((b*31 + ci)*128 + ih)*128 + iw];
        sIn[idx] = v;
    }
    __syncthreads();
    int cog = t & 15, owg = t >> 4;   // co = cog*4+cc, ow = owg*4+q
    float acc[4][4];
    #pragma unroll
    for (int q = 0; q < 4; q++)
        #pragma unroll
        for (int cc = 0; cc < 4; cc++) acc[q][cc] = 0.f;
    for (int ci = 0; ci < 31; ci++) {
        #pragma unroll
        for (int r = 0; r < 3; r++) {
            int ib = (ci*3 + r)*130 + owg*8;
            #pragma unroll
            for (int kw = 0; kw < 3; kw++) {
                float4 wv = *(const float4*)&g_wc[((ci*9 + r*3 + kw)*64) + cog*4];
                #pragma unroll
                for (int q = 0; q < 4; q++) {
                    float iv = sIn[ib + 2*q + kw];
                    acc[q][0] += iv * wv.x;
                    acc[q][1] += iv * wv.y;
                    acc[q][2] += iv * wv.z;
                    acc[q][3] += iv * wv.w;
                }
            }
        }
    }
    float4 bv = *(const float4*)&bias[cog*4];
    #pragma unroll
    for (int q = 0; q < 4; q++) {
        int node = b*4096 + oh*64 + owg*4 + q;
        float4 o;
        o.x = acc[q][0] + bv.x; o.y = acc[q][1] + bv.y;
        o.z = acc[q][2] + bv.z; o.w = acc[q][3] + bv.w;
        *(float4*)&g_y[node*64 + cog*4] = o;
    }
}

// ---------------- K2: squared norms ----------------
__global__ void sq_kernel() {
    int node = blockIdx.x*8 + (threadIdx.x >> 5);
    int lane = threadIdx.x & 31;
    const float* p = &g_y[node*64];
    float a = p[lane], b = p[lane + 32];
    float v = a*a + b*b;
    #pragma unroll
    for (int off = 16; off; off >>= 1) v += __shfl_down_sync(0xffffffffu, v, off);
    if (lane == 0) g_sq[node] = v;
}

// ---------------- K3: fused Gram + top-7 kNN (register tiled) ----------------
#define TI 32
#define TJ 128
__global__ void __launch_bounds__(256, 2) knn_kernel() {
    __shared__ __align__(16) float yi[TI*68];
    __shared__ __align__(16) float yj[TJ*68];
    __shared__ float sqi[TI];
    __shared__ float sqj[TJ];
    int t = threadIdx.x;
    int i0 = blockIdx.x * TI;
    int base = i0 & ~4095;
    int ig = t >> 5, jg = t & 31;     // 4 i-rows = ig*4+ii ; 4 j-cols = jg+32m

    for (int idx = t; idx < TI*16; idx += 256) {
        int row = idx >> 4, c4 = idx & 15;
        *(float4*)&yi[row*68 + c4*4] = *(const float4*)&g_y[(i0 + row)*64 + c4*4];
    }
    if (t < TI) sqi[t] = g_sq[i0 + t];
    __syncthreads();
    float sqir[4];
    #pragma unroll
    for (int ii = 0; ii < 4; ii++) sqir[ii] = sqi[ig*4 + ii];

    ull top[4][7];
    #pragma unroll
    for (int ii = 0; ii < 4; ii++)
        #pragma unroll
        for (int s = 0; s < 7; s++) top[ii][s] = ULLMAX;

    for (int jt = 0; jt < NPB; jt += TJ) {
        __syncthreads();
        for (int idx = t; idx < TJ*16; idx += 256) {
            int row = idx >> 4, c4 = idx & 15;
            *(float4*)&yj[row*68 + c4*4] = *(const float4*)&g_y[(base + jt + row)*64 + c4*4];
        }
        if (t < TJ) sqj[t] = g_sq[base + jt + t];
        __syncthreads();

        float acc[4][4];
        #pragma unroll
        for (int ii = 0; ii < 4; ii++)
            #pragma unroll
            for (int m = 0; m < 4; m++) acc[ii][m] = 0.f;

        #pragma unroll
        for (int c = 0; c < 64; c += 4) {
            float4 av[4], bv[4];
            #pragma unroll
            for (int ii = 0; ii < 4; ii++) av[ii] = *(const float4*)&yi[(ig*4 + ii)*68 + c];
            #pragma unroll
            for (int m = 0; m < 4; m++)  bv[m] = *(const float4*)&yj[(jg + 32*m)*68 + c];
            #pragma unroll
            for (int ii = 0; ii < 4; ii++)
                #pragma unroll
                for (int m = 0; m < 4; m++) {
                    acc[ii][m] += av[ii].x*bv[m].x + av[ii].y*bv[m].y
                                + av[ii].z*bv[m].z + av[ii].w*bv[m].w;
                }
        }

        float sqjv[4];
        #pragma unroll
        for (int m = 0; m < 4; m++) sqjv[m] = sqj[jg + 32*m];
        #pragma unroll
        for (int ii = 0; ii < 4; ii++) {
            float si = sqir[ii];
            #pragma unroll
            for (int m = 0; m < 4; m++) {
                float d2 = si + sqjv[m] - 2.f*acc[ii][m];
                if (d2 < 0.f) d2 = 0.f;
                ull key = ((ull)__float_as_uint(d2) << 32) | (unsigned)(jt + jg + 32*m);
                if (key < top[ii][6]) {
                    top[ii][6] = key;
                    #pragma unroll
                    for (int s = 5; s >= 0; s--)
                        if (top[ii][s+1] < top[ii][s]) {
                            ull tmp = top[ii][s]; top[ii][s] = top[ii][s+1]; top[ii][s+1] = tmp;
                        }
                }
            }
        }
    }

    // merge 32 sorted 7-lists per row via warp reduction (4 passes over ii)
    ull* keys = (ull*)yj;             // 256*7 ull = 14336B, overlays yj
    int lane = jg;
    for (int ii = 0; ii < 4; ii++) {
        __syncthreads();
        #pragma unroll
        for (int s = 0; s < 7; s++) keys[t*7 + s] = top[ii][s];
        __syncthreads();
        int r = ig*4 + ii;
        ull mine[7];
        #pragma unroll
        for (int s = 0; s < 7; s++) mine[s] = keys[(ig*32 + lane)*7 + s];
        #pragma unroll
        for (int s = 0; s < 7; s++) {
            ull cur = mine[0];
            ull m = cur;
            #pragma unroll
            for (int off = 16; off; off >>= 1) {
                ull o = __shfl_down_sync(0xffffffffu, m, off);
                if (o < m) m = o;
            }
            m = __shfl_sync(0xffffffffu, m, 0);
            if (cur == m) {
                mine[0]=mine[1]; mine[1]=mine[2]; mine[2]=mine[3];
                mine[3]=mine[4]; mine[4]=mine[5]; mine[5]=mine[6]; mine[6]=ULLMAX;
            }
            if (lane == 0) g_nbr[(i0 + r)*7 + s] = (int)(unsigned)(m & 0xffffffffu);
        }
    }
}

// ---------------- K4: proj heads 0/1 (tiled GEMM, f-scalars folded) ----------------
__global__ void proj01_kernel(const float* __restrict__ W0,
                              const float* __restrict__ W1) {
    __shared__ float ys[32*68];
    __shared__ float Wc[64*136];
    int t = threadIdx.x;
    int i0 = blockIdx.x * 32;
    for (int idx = t; idx < 64*136; idx += 256) {
        int k = idx / 136, c = idx % 136;
        float v = 0.f;
        if (c < 64) v = W0[k*64 + c];
        else if (c < 128) v = W1[k*64 + c - 64];
        else if (c < 132) v = g_va[(c - 128)*64 + k];
        Wc[idx] = v;
    }
    for (int idx = t; idx < 2048; idx += 256) {
        int n = idx >> 6, k = idx & 63;
        ys[n*68 + k] = g_y[(i0 + n)*64 + k];
    }
    __syncthreads();
    int cg = t & 31, ng = t >> 5;     // 4 nodes, cols cg+32m (m<4) and 128+cg (cg<4)
    float acc[4][5];
    #pragma unroll
    for (int nn = 0; nn < 4; nn++)
        #pragma unroll
        for (int m = 0; m < 5; m++) acc[nn][m] = 0.f;
    for (int k = 0; k < 64; k++) {
        float w0 = Wc[k*136 + cg];
        float w1 = Wc[k*136 + cg + 32];
        float w2 = Wc[k*136 + cg + 64];
        float w3 = Wc[k*136 + cg + 96];
        float w4 = (cg < 4) ? Wc[k*136 + 128 + cg] : 0.f;
        #pragma unroll
        for (int nn = 0; nn < 4; nn++) {
            float yv = ys[(ng*4 + nn)*68 + k];
            acc[nn][0] += yv*w0; acc[nn][1] += yv*w1;
            acc[nn][2] += yv*w2; acc[nn][3] += yv*w3;
            acc[nn][4] += yv*w4;
        }
    }
    #pragma unroll
    for (int nn = 0; nn < 4; nn++) {
        int node = i0 + ng*4 + nn;
        g_h0[node*64 + cg]      = acc[nn][0];
        g_h0[node*64 + cg + 32] = acc[nn][1];
        g_h1[node*64 + cg]      = acc[nn][2];
        g_h1[node*64 + cg + 32] = acc[nn][3];
        if (cg == 0) g_f10[node] = acc[nn][4];
        else if (cg == 1) g_f20[node] = acc[nn][4];
        else if (cg == 2) g_f11[node] = acc[nn][4];
        else if (cg == 3) g_f21[node] = acc[nn][4];
    }
}

// ---------------- K5: sparse attention agg heads 0/1 + relu ----------------
__global__ void agg01_kernel() {
    int t = threadIdx.x;
    int node = blockIdx.x*2 + (t >> 7);
    int head = (t >> 6) & 1, c = t & 63;
    int bb = node & ~4095;
    int nb[7];
    #pragma unroll
    for (int s = 0; s < 7; s++) nb[s] = bb + g_nbr[node*7 + s];
    const float* f1 = head ? g_f11 : g_f10;
    const float* f2 = head ? g_f21 : g_f20;
    const float* h  = head ? g_h1  : g_h0;
    float fi = f1[node];
    float e[7], m = -3.4e38f;
    #pragma unroll
    for (int s = 0; s < 7; s++) {
        float v = fi + f2[nb[s]];
        v = v > 0.f ? v : 0.2f*v;
        e[s] = v; if (v > m) m = v;
    }
    float sum = 0.f;
    #pragma unroll
    for (int s = 0; s < 7; s++) { e[s] = expf(e[s] - m); sum += e[s]; }
    float inv = 1.f / sum;
    float acc = 0.f;
    #pragma unroll
    for (int s = 0; s < 7; s++) acc += e[s]*inv * h[nb[s]*64 + c];
    acc = acc > 0.f ? acc : 0.f;
    g_hcat[node*128 + head*64 + c] = acc;
}

// ---------------- K6: out-head projection (tiled GEMM, f folded) ----------------
__global__ void projout_kernel(const float* __restrict__ W_out) {
    __shared__ float hs[16*136];
    __shared__ float Wo[128*72];
    int t = threadIdx.x;
    int i0 = blockIdx.x * 16;
    for (int idx = t; idx < 128*72; idx += 256) {
        int k = idx / 72, c = idx % 72;
        float v = 0.f;
        if (c < 64) v = W_out[k*64 + c];
        else if (c == 64) v = g_vaO[k];
        else if (c == 65) v = g_vaO[128 + k];
        Wo[idx] = v;
    }
    for (int idx = t; idx < 2048; idx += 256) {
        int n = idx >> 7, k = idx & 127;
        hs[n*136 + k] = g_hcat[(i0 + n)*128 + k];
    }
    __syncthreads();
    int cg = t & 31, ng = t >> 5;     // 2 nodes, cols cg, cg+32, and 64+cg (cg<2)
    float acc[2][3];
    #pragma unroll
    for (int nn = 0; nn < 2; nn++)
        #pragma unroll
        for (int m = 0; m < 3; m++) acc[nn][m] = 0.f;
    for (int k = 0; k < 128; k++) {
        float w0 = Wo[k*72 + cg];
        float w1 = Wo[k*72 + cg + 32];
        float w2 = (cg < 2) ? Wo[k*72 + 64 + cg] : 0.f;
        #pragma unroll
        for (int nn = 0; nn < 2; nn++) {
            float yv = hs[(ng*2 + nn)*136 + k];
            acc[nn][0] += yv*w0; acc[nn][1] += yv*w1; acc[nn][2] += yv*w2;
        }
    }
    #pragma unroll
    for (int nn = 0; nn < 2; nn++) {
        int node = i0 + ng*2 + nn;
        g_ho[node*64 + cg]      = acc[nn][0];
        g_ho[node*64 + cg + 32] = acc[nn][1];
        if (cg == 0) g_f1o[node] = acc[nn][2];
        else if (cg == 1) g_f2o[node] = acc[nn][2];
    }
}

// ---------------- K7: out-head agg + elu + log_softmax ----------------
__global__ void aggout_kernel() {
    __shared__ float wmax[4][2];
    __shared__ float wsum[4][2];
    int t = threadIdx.x;
    int ln = t >> 6, c = t & 63;
    int node = blockIdx.x*4 + ln;
    int lane = t & 31, wh = (t >> 5) & 1;
    int bb = node & ~4095;
    int nb[7];
    #pragma unroll
    for (int s = 0; s < 7; s++) nb[s] = bb + g_nbr[node*7 + s];
    float fi = g_f1o[node];
    float e[7], m = -3.4e38f;
    #pragma unroll
    for (int s = 0; s < 7; s++) {
        float v = fi + g_f2o[nb[s]];
        v = v > 0.f ? v : 0.2f*v;
        e[s] = v; if (v > m) m = v;
    }
    float sum = 0.f;
    #pragma unroll
    for (int s = 0; s < 7; s++) { e[s] = expf(e[s] - m); sum += e[s]; }
    float inv = 1.f / sum;
    float acc = 0.f;
    #pragma unroll
    for (int s = 0; s < 7; s++) acc += e[s]*inv * g_ho[nb[s]*64 + c];
    float v = acc > 0.f ? acc : (expf(acc) - 1.f);

    float mx = v;
    #pragma unroll
    for (int off = 16; off; off >>= 1) mx = fmaxf(mx, __shfl_down_sync(0xffffffffu, mx, off));
    if (lane == 0) wmax[ln][wh] = mx;
    __syncthreads();
    mx = fmaxf(wmax[ln][0], wmax[ln][1]);
    float p = expf(v - mx);
    float ssum = p;
    #pragma unroll
    for (int off = 16; off; off >>= 1) ssum += __shfl_down_sync(0xffffffffu, ssum, off);
    if (lane == 0) wsum[ln][wh] = ssum;
    __syncthreads();
    float tot = wsum[ln][0] + wsum[ln][1];
    g_outn[node*64 + c] = v - mx - logf(tot);
}

// ---------------- K8: ConvTranspose2d (register tiled) ----------------
__global__ void convt_kernel(const float* __restrict__ b_last, float* __restrict__ out) {
    int b = blockIdx.x >> 7;
    int oh = blockIdx.x & 127;
    __shared__ __align__(16) float sin[2][64*68];
    int khs[2], ihs[2];
    int cnt = 0;
    for (int kh = 0; kh < 3; kh++) {
        int num = oh + 1 - kh;
        if (num & 1) continue;
        int ih = num >> 1;
        if (ih < 0 || ih >= 64) continue;
        khs[cnt] = kh; ihs[cnt] = ih; cnt++;
    }
    int t = threadIdx.x;
    for (int r = 0; r < cnt; r++) {
        const float* src = &g_outn[((b << 12) + ihs[r]*64)*64];
        for (int idx = t; idx < 1024; idx += 256) {
            int iw = idx >> 4, c4 = idx & 15;
            *(float4*)&sin[r][iw*68 + c4*4] = *(const float4*)&src[iw*64 + c4*4];
        }
    }
    __syncthreads();
    int cog = t & 15, owg = t >> 4;   // co = cog*4+cc, ow = owg*8+q
    float acc[8][4];
    #pragma unroll
    for (int q = 0; q < 8; q++)
        #pragma unroll
        for (int cc = 0; cc < 4; cc++) acc[q][cc] = 0.f;

    for (int r = 0; r < cnt; r++) {
        int kh = khs[r];
        #pragma unroll
        for (int kw = 0; kw < 3; kw++) {
            int iwq[4]; bool vq[4];
            #pragma unroll
            for (int u = 0; u < 4; u++) {
                int q = ((kw + 1) & 1) + 2*u;
                int num = owg*8 + q + 1 - kw;
                int iw = num >> 1;
                iwq[u] = iw;
                vq[u] = (num >= 0) && (iw < 64);
            }
            const float* wbase = &g_wt[(kh*3 + kw)*4096 + cog*4];
            for (int ci0 = 0; ci0 < 64; ci0 += 4) {
                float4 w0 = *(const float4*)&wbase[(ci0+0)*64];
                float4 w1 = *(const float4*)&wbase[(ci0+1)*64];
                float4 w2 = *(const float4*)&wbase[(ci0+2)*64];
                float4 w3 = *(const float4*)&wbase[(ci0+3)*64];
                #pragma unroll
                for (int u = 0; u < 4; u++) {
                    if (!vq[u]) continue;
                    int q = ((kw + 1) & 1) + 2*u;
                    float4 iv = *(const float4*)&sin[r][iwq[u]*68 + ci0];
                    #pragma unroll
                    for (int cc = 0; cc < 4; cc++) {
                        float wv0 = (&w0.x)[cc], wv1 = (&w1.x)[cc],
                              wv2 = (&w2.x)[cc], wv3 = (&w3.x)[cc];
                        acc[q][cc] += iv.x*wv0 + iv.y*wv1 + iv.z*wv2 + iv.w*wv3;
                    }
                }
            }
        }
    }
    #pragma unroll
    for (int cc = 0; cc < 4; cc++) {
        int co = cog*4 + cc;
        float bv = b_last[co];
        float4 o0, o1;
        o0.x = acc[0][cc]+bv; o0.y = acc[1][cc]+bv; o0.z = acc[2][cc]+bv; o0.w = acc[3][cc]+bv;
        o1.x = acc[4][cc]+bv; o1.y = acc[5][cc]+bv; o1.z = acc[6][cc]+bv; o1.w = acc[7][cc]+bv;
        float* dst = &out[((b*64 + co)*128 + oh)*128 + owg*8];
        *(float4*)&dst[0] = o0;
        *(float4*)&dst[4] = o1;
    }
}

// ---------------- launcher ----------------
extern "C" void kernel_launch(void* const* d_in, const int* in_sizes, int n_in,
                              void* d_out, int out_size) {
    const float* x      = (const float*)d_in[0];
    const float* w_head = (const float*)d_in[1];
    const float* b_head = (const float*)d_in[2];
    const float* W0     = (const float*)d_in[3];
    const float* a0     = (const float*)d_in[4];
    const float* W1     = (const float*)d_in[5];
    const float* a1     = (const float*)d_in[6];
    const float* W_out  = (const float*)d_in[7];
    const float* a_out  = (const float*)d_in[8];
    const float* w_last = (const float*)d_in[9];
    const float* b_last = (const float*)d_in[10];
    float* out = (float*)d_out;

    prep_kernel<<<216, 256>>>(w_last, w_head, W0, a0, W1, a1, W_out, a_out);
    conv_head_kernel<<<128, 256>>>(x, b_head);
    sq_kernel<<<1024, 256>>>();
    knn_kernel<<<NTOT/TI, 256>>>();
    proj01_kernel<<<NTOT/32, 256>>>(W0, W1);
    agg01_kernel<<<NTOT/2, 256>>>();
    projout_kernel<<<NTOT/16, 256>>>(W_out);
    aggout_kernel<<<NTOT/4, 256>>>();
    convt_kernel<<<NB*128, 256>>>(b_last, out);
}